// round 2
// baseline (speedup 1.0000x reference)
#include <cuda_runtime.h>
#include <math.h>

#define GX 256
#define GY 256
#define NBATCH 4
#define SENTKEY (NBATCH*GX*GY)        /* 262144 */
#define NKEY (SENTKEY+1)              /* 262145 */
#define NSEG (SENTKEY+2)              /* 262146 */
#define MAXN 1000000
#define NBLK ((NKEY+1023)/1024)       /* 257 */
#define BN_EPS 1e-3f
#define FULLMASK 0xffffffffu
#define ENC_NEG_INF 0x007FFFFFu

// ---------------- static scratch ----------------
static __device__ int   g_keys[MAXN];
static __device__ int   g_order[MAXN];
static __device__ int   g_cnt[NKEY];
static __device__ int   g_cursor[NKEY];
static __device__ int   g_rank[NKEY];
static __device__ int   g_off[NKEY];
static __device__ float g_sumxyz[NKEY*3];
static __device__ int   g_blkP[NBLK], g_blkC[NBLK], g_offP[NBLK], g_offC[NBLK];
static __device__ int   g_U, g_sentseg, g_nsent;
static __device__ int   g_segstart[NSEG], g_segcnt[NSEG], g_keyofrank[NSEG];
static __device__ float g_mean[NSEG*3];
static __device__ float g_sum0[32], g_sumsq0[32];
static __device__ float g_a0[32], g_b0v[32];
static __device__ float g_sumz[128], g_sumz2[128];
static __device__ float g_a1[128], g_b1v[128];
static __device__ int   g_xm0sent[32];
static __device__ unsigned g_sentpre[128];
static __device__ float g_x0sent[(size_t)MAXN*32];       // 128 MB
static __device__ float g_pre[(size_t)NSEG*128];         // 134 MB

static __device__ __forceinline__ unsigned encf(float f){
    unsigned b = __float_as_uint(f);
    return (b & 0x80000000u) ? ~b : (b | 0x80000000u);
}
static __device__ __forceinline__ float decf(unsigned e){
    unsigned b = (e & 0x80000000u) ? (e & 0x7FFFFFFFu) : ~e;
    return __uint_as_float(b);
}

// ---------------- init ----------------
__global__ void kInit(){
    int i = blockIdx.x*blockDim.x + threadIdx.x;
    int stride = gridDim.x*blockDim.x;
    for (int idx=i; idx<NKEY*3; idx+=stride) g_sumxyz[idx]=0.f;
    for (int idx=i; idx<NKEY; idx+=stride){ g_cnt[idx]=0; g_cursor[idx]=0; }
    if (i < 128){ g_sumz[i]=0.f; g_sumz2[i]=0.f; g_sentpre[i]=ENC_NEG_INF; }
    if (i < 32){ g_sum0[i]=0.f; g_sumsq0[i]=0.f; g_xm0sent[i]=0; }
    if (i == 0){ g_sentseg=-1; g_nsent=0; }
}

// default coords for all rows (overwritten for real segments) + grid
__global__ void kFill(float* __restrict__ out){
    int i = blockIdx.x*blockDim.x + threadIdx.x;
    int stride = gridDim.x*blockDim.x;
    float* oc = out + (size_t)NSEG*128;
    for (int r=i; r<NSEG; r+=stride){
        oc[(size_t)r*3+0]=4.0f; oc[(size_t)r*3+1]=0.0f; oc[(size_t)r*3+2]=0.0f;
    }
    if (i==0){
        out[(size_t)NSEG*128 + (size_t)NSEG*3 + 0] = 256.0f;
        out[(size_t)NSEG*128 + (size_t)NSEG*3 + 1] = 256.0f;
    }
}

// ---------------- A: keys + histogram + xyz sums ----------------
__global__ void kA(const float* __restrict__ pts, int n){
    int i = blockIdx.x*blockDim.x + threadIdx.x;
    int stride = gridDim.x*blockDim.x;
    for (int p=i; p<n; p+=stride){
        const float* q = pts + (size_t)p*6;
        float b=q[0], x=q[1], y=q[2], z=q[3];
        float fx = __fdiv_rn(x - (-51.2f), 0.4f);
        float fy = __fdiv_rn(y - (-51.2f), 0.4f);
        bool m = (fx >= 0.f) && (fx < 256.f) && (fy >= 0.f) && (fy < 256.f);
        int cix=(int)fx, ciy=(int)fy;
        int bi=(int)b;
        int key = m ? ((bi*GX + cix)*GY + ciy) : SENTKEY;
        g_keys[p]=key;
        atomicAdd(&g_cnt[key],1);
        atomicAdd(&g_sumxyz[key*3+0],x);
        atomicAdd(&g_sumxyz[key*3+1],y);
        atomicAdd(&g_sumxyz[key*3+2],z);
    }
}

// ---------------- B: two-level scan over keys ----------------
__global__ void kB1(){
    int tid = threadIdx.x;
    int idx = blockIdx.x*1024 + tid;
    int c = (idx<NKEY)? g_cnt[idx] : 0;
    int p = (c>0)? 1:0;
    #pragma unroll
    for (int o=16;o;o>>=1){ p+=__shfl_down_sync(FULLMASK,p,o); c+=__shfl_down_sync(FULLMASK,c,o); }
    __shared__ int sp[32], sc[32];
    if ((tid&31)==0){ sp[tid>>5]=p; sc[tid>>5]=c; }
    __syncthreads();
    if (tid<32){
        p=sp[tid]; c=sc[tid];
        #pragma unroll
        for (int o=16;o;o>>=1){ p+=__shfl_down_sync(FULLMASK,p,o); c+=__shfl_down_sync(FULLMASK,c,o); }
        if (tid==0){ g_blkP[blockIdx.x]=p; g_blkC[blockIdx.x]=c; }
    }
}

__global__ void kB2(){
    __shared__ int sp[512], sc[512];
    int t = threadIdx.x;
    int p = (t<NBLK)? g_blkP[t]:0;
    int c = (t<NBLK)? g_blkC[t]:0;
    sp[t]=p; sc[t]=c; __syncthreads();
    for (int o=1;o<512;o<<=1){
        int vp=(t>=o)?sp[t-o]:0, vc=(t>=o)?sc[t-o]:0;
        __syncthreads();
        sp[t]+=vp; sc[t]+=vc;
        __syncthreads();
    }
    if (t<NBLK){ g_offP[t]=sp[t]-p; g_offC[t]=sc[t]-c; }
    if (t==NBLK-1) g_U = sp[t];
}

__global__ void kB3(float* __restrict__ out){
    __shared__ int sp[1024], sc[1024];
    int tid = threadIdx.x;
    int idx = blockIdx.x*1024 + tid;
    int c = (idx<NKEY)? g_cnt[idx]:0;
    int pr = (c>0)? 1:0;
    sp[tid]=pr; sc[tid]=c; __syncthreads();
    for (int o=1;o<1024;o<<=1){
        int vp=(tid>=o)?sp[tid-o]:0, vc=(tid>=o)?sc[tid-o]:0;
        __syncthreads();
        sp[tid]+=vp; sc[tid]+=vc;
        __syncthreads();
    }
    if (idx<NKEY){
        int r  = sp[tid]-pr + g_offP[blockIdx.x];
        int of = sc[tid]-c  + g_offC[blockIdx.x];
        g_rank[idx]=r; g_off[idx]=of;
        if (pr){
            g_keyofrank[r]=idx; g_segstart[r]=of; g_segcnt[r]=c;
            float fc = (float)c;
            g_mean[r*3+0]=__fdiv_rn(g_sumxyz[idx*3+0],fc);
            g_mean[r*3+1]=__fdiv_rn(g_sumxyz[idx*3+1],fc);
            g_mean[r*3+2]=__fdiv_rn(g_sumxyz[idx*3+2],fc);
            int b=idx>>16, cx=(idx>>8)&255, cy=idx&255;
            float* oc = out + (size_t)NSEG*128 + (size_t)r*3;
            oc[0]=(float)b; oc[1]=(float)cy; oc[2]=(float)cx;
            if (idx==SENTKEY){ g_sentseg=r; g_nsent=c; }
        }
    }
}

// ---------------- C: counting-sort scatter ----------------
__global__ void kC(int n){
    int i = blockIdx.x*blockDim.x + threadIdx.x;
    int stride = gridDim.x*blockDim.x;
    for (int p=i; p<n; p+=stride){
        int key = g_keys[p];
        int pos = g_off[key] + atomicAdd(&g_cursor[key],1);
        g_order[pos] = p;
    }
}

// pre-affine x0 for a point
static __device__ __forceinline__ float compX0(const float* __restrict__ pts, int p,
    float mx, float my, float mzv, float ccx, float ccy, const float* __restrict__ w0c)
{
    const float2* q = reinterpret_cast<const float2*>(pts + (size_t)p*6);
    float2 q0=__ldg(q), q1=__ldg(q+1), q2=__ldg(q+2);
    float x=q0.y, y=q1.x, z=q1.y;
    float s =  x*w0c[0] + y*w0c[1] + z*w0c[2] + q2.x*w0c[3] + q2.y*w0c[4]
            + (x-mx)*w0c[5] + (y-my)*w0c[6] + (z-mzv)*w0c[7]
            + (x-ccx)*w0c[8] + (y-ccy)*w0c[9];
    return s;
}

// ---------------- BN0 stats over valid points ----------------
__global__ void __launch_bounds__(256) kBN0(const float* __restrict__ pts,
                                            const float* __restrict__ w0, int n){
    int gtid = blockIdx.x*blockDim.x + threadIdx.x;
    int w = gtid>>5, lane = gtid&31;
    int nwarps = (gridDim.x*blockDim.x)>>5;
    float w0c[10];
    #pragma unroll
    for (int j=0;j<10;j++) w0c[j]=w0[j*32+lane];
    float s=0.f, s2=0.f;
    for (int p=w; p<n; p+=nwarps){
        int key = g_keys[p];
        if (key == SENTKEY) continue;
        int r = g_rank[key];
        float mx=g_mean[r*3+0], my=g_mean[r*3+1], mzv=g_mean[r*3+2];
        float ccx=(float)((key>>8)&255)*0.4f + 0.2f + (-51.2f);
        float ccy=(float)(key&255)*0.4f + 0.2f + (-51.2f);
        float x0 = compX0(pts,p,mx,my,mzv,ccx,ccy,w0c);
        s += x0; s2 += x0*x0;
    }
    atomicAdd(&g_sum0[lane], s);
    atomicAdd(&g_sumsq0[lane], s2);
}

// ---------------- BN0 params ----------------
__global__ void kD1(const float* __restrict__ g0, const float* __restrict__ b0, int n){
    int c = threadIdx.x; // 32
    float cnt = (float)(n - g_cnt[SENTKEY]);
    float mu = g_sum0[c]/cnt;
    float var = g_sumsq0[c]/cnt - mu*mu;
    var = fmaxf(var, 0.f);
    float a = g0[c] / sqrtf(var + BN_EPS);
    g_a0[c]=a; g_b0v[c]=b0[c]-mu*a;
}

// ---------------- sentinel: layer0 ----------------
__global__ void __launch_bounds__(256) kS1(const float* __restrict__ pts,
                                           const float* __restrict__ w0){
    int gtid = blockIdx.x*blockDim.x + threadIdx.x;
    int w = gtid>>5, lane = gtid&31;
    int nwarps = (gridDim.x*blockDim.x)>>5;
    int nsent = g_nsent;
    if (nsent == 0) return;
    int ss = g_sentseg;
    int st = g_segstart[ss];
    float mx=g_mean[ss*3+0], my=g_mean[ss*3+1], mzv=g_mean[ss*3+2];
    float w0c[10];
    #pragma unroll
    for (int j=0;j<10;j++) w0c[j]=w0[j*32+lane];
    float a0=g_a0[lane], b0v=g_b0v[lane];
    float runmax = 0.f;
    for (int i=w; i<nsent; i+=nwarps){
        int p = g_order[st+i];
        const float2* q = reinterpret_cast<const float2*>(pts + (size_t)p*6);
        float2 q0=__ldg(q), q1=__ldg(q+1);
        float x=q0.y, y=q1.x;
        float fx=__fdiv_rn(x - (-51.2f), 0.4f);
        float fy=__fdiv_rn(y - (-51.2f), 0.4f);
        int cix=(int)fx, ciy=(int)fy;
        float ccx=(float)cix*0.4f + 0.2f + (-51.2f);
        float ccy=(float)ciy*0.4f + 0.2f + (-51.2f);
        float x0 = compX0(pts,p,mx,my,mzv,ccx,ccy,w0c);
        float x0r = fmaxf(a0*x0 + b0v, 0.f);
        g_x0sent[(size_t)i*32 + lane] = x0r;
        runmax = fmaxf(runmax, x0r);
    }
    atomicMax(&g_xm0sent[lane], __float_as_int(runmax)); // nonneg floats: int order == float order
}

// ---------------- mega: warp per valid segment ----------------
__global__ void __launch_bounds__(256) kMega(const float* __restrict__ pts,
                                             const float* __restrict__ w0,
                                             const float* __restrict__ w1){
    __shared__ float4 w1s4[2048];   // 32 KB: full w1 (64x128)
    __shared__ float sacc[256];
    int tid = threadIdx.x;
    for (int i=tid; i<2048; i+=256) w1s4[i] = reinterpret_cast<const float4*>(w1)[i];
    sacc[tid] = 0.f;
    __syncthreads();

    int gtid = blockIdx.x*blockDim.x + tid;
    int w = gtid>>5, lane = gtid&31;
    int nwarps = (gridDim.x*blockDim.x)>>5;
    int U = g_U, sentseg = g_sentseg;

    float w0c[10];
    #pragma unroll
    for (int j=0;j<10;j++) w0c[j]=w0[j*32+lane];
    float a0=g_a0[lane], b0v=g_b0v[lane];
    float sz0=0.f,sz1=0.f,sz2v=0.f,sz3=0.f;
    float sq0=0.f,sq1=0.f,sq2=0.f,sq3=0.f;

    for (int r=w; r<U; r+=nwarps){
        if (r==sentseg) continue;
        int st=g_segstart[r], cn=g_segcnt[r], key=g_keyofrank[r];
        float mx=g_mean[r*3+0], my=g_mean[r*3+1], mzv=g_mean[r*3+2];
        float ccx=(float)((key>>8)&255)*0.4f + 0.2f + (-51.2f);
        float ccy=(float)(key&255)*0.4f + 0.2f + (-51.2f);

        // pass 1: xm0 (lane = layer-0 channel)
        float run0 = 0.f;
        for (int i=0;i<cn;i++){
            int p = g_order[st+i];
            float x0r = fmaxf(a0*compX0(pts,p,mx,my,mzv,ccx,ccy,w0c) + b0v, 0.f);
            run0 = fmaxf(run0, x0r);
        }
        // zb = xm0 @ w1b ; lane owns z-channels lane*4..+3
        float zb0=0.f,zb1=0.f,zb2=0.f,zb3=0.f;
        #pragma unroll
        for (int k=0;k<32;k++){
            float v = __shfl_sync(FULLMASK, run0, k);
            float4 wv = w1s4[1024 + k*32 + lane];
            zb0=fmaf(v,wv.x,zb0); zb1=fmaf(v,wv.y,zb1); zb2=fmaf(v,wv.z,zb2); zb3=fmaf(v,wv.w,zb3);
        }
        // pass 2: za per point (2-point groups), BN1 sums, running max of z
        float m0=-INFINITY,m1=-INFINITY,m2=-INFINITY,m3=-INFINITY;
        for (int i=0;i<cn;i+=2){
            int pa = g_order[st+i];
            float xa = fmaxf(a0*compX0(pts,pa,mx,my,mzv,ccx,ccy,w0c) + b0v, 0.f);
            bool hasb = (i+1<cn);
            float xb = 0.f;
            if (hasb){
                int pb = g_order[st+i+1];
                xb = fmaxf(a0*compX0(pts,pb,mx,my,mzv,ccx,ccy,w0c) + b0v, 0.f);
            }
            float a0_=0.f,a1_=0.f,a2_=0.f,a3_=0.f;
            float b0_=0.f,b1_=0.f,b2_=0.f,b3_=0.f;
            #pragma unroll
            for (int k=0;k<32;k++){
                float va=__shfl_sync(FULLMASK, xa, k);
                float vb=__shfl_sync(FULLMASK, xb, k);
                float4 wv = w1s4[k*32 + lane];
                a0_=fmaf(va,wv.x,a0_); a1_=fmaf(va,wv.y,a1_); a2_=fmaf(va,wv.z,a2_); a3_=fmaf(va,wv.w,a3_);
                b0_=fmaf(vb,wv.x,b0_); b1_=fmaf(vb,wv.y,b1_); b2_=fmaf(vb,wv.z,b2_); b3_=fmaf(vb,wv.w,b3_);
            }
            float z0=a0_+zb0, z1=a1_+zb1, z2=a2_+zb2, z3=a3_+zb3;
            sz0+=z0; sz1+=z1; sz2v+=z2; sz3+=z3;
            sq0=fmaf(z0,z0,sq0); sq1=fmaf(z1,z1,sq1); sq2=fmaf(z2,z2,sq2); sq3=fmaf(z3,z3,sq3);
            m0=fmaxf(m0,z0); m1=fmaxf(m1,z1); m2=fmaxf(m2,z2); m3=fmaxf(m3,z3);
            if (hasb){
                z0=b0_+zb0; z1=b1_+zb1; z2=b2_+zb2; z3=b3_+zb3;
                sz0+=z0; sz1+=z1; sz2v+=z2; sz3+=z3;
                sq0=fmaf(z0,z0,sq0); sq1=fmaf(z1,z1,sq1); sq2=fmaf(z2,z2,sq2); sq3=fmaf(z3,z3,sq3);
                m0=fmaxf(m0,z0); m1=fmaxf(m1,z1); m2=fmaxf(m2,z2); m3=fmaxf(m3,z3);
            }
        }
        reinterpret_cast<float4*>(g_pre)[(size_t)r*32 + lane] = make_float4(m0,m1,m2,m3);
    }

    // block-level reduction of BN1 partials, then 1 global atomic per slot
    atomicAdd(&sacc[lane*8+0], sz0); atomicAdd(&sacc[lane*8+1], sz1);
    atomicAdd(&sacc[lane*8+2], sz2v); atomicAdd(&sacc[lane*8+3], sz3);
    atomicAdd(&sacc[lane*8+4], sq0); atomicAdd(&sacc[lane*8+5], sq1);
    atomicAdd(&sacc[lane*8+6], sq2); atomicAdd(&sacc[lane*8+7], sq3);
    __syncthreads();
    if (tid < 256){
        int l = tid>>3, j = tid&7;
        float v = sacc[tid];
        if (j<4) atomicAdd(&g_sumz[l*4+j], v);
        else     atomicAdd(&g_sumz2[l*4+(j-4)], v);
    }
}

// ---------------- sentinel: layer1 max ----------------
__global__ void __launch_bounds__(128) kS2(const float* __restrict__ w1){
    int c = threadIdx.x; // 0..127
    int nsent = g_nsent;
    if (nsent == 0) return;
    __shared__ float xm[32];
    __shared__ float x0s[32];
    if (c < 32) xm[c] = __int_as_float(g_xm0sent[c]);
    __syncthreads();
    float zb = 0.f;
    #pragma unroll
    for (int k=0;k<32;k++) zb = fmaf(xm[k], w1[(k+32)*128 + c], zb);

    int per = (nsent + gridDim.x - 1)/gridDim.x;
    int i0 = blockIdx.x*per;
    int i1 = min(i0+per, nsent);
    if (i0 >= i1) return;
    float mz = -INFINITY;
    for (int i=i0;i<i1;i++){
        __syncthreads();
        if (c < 32) x0s[c] = g_x0sent[(size_t)i*32 + c];
        __syncthreads();
        float za = 0.f;
        #pragma unroll
        for (int k=0;k<32;k++) za = fmaf(x0s[k], w1[k*128 + c], za);
        mz = fmaxf(mz, za);
    }
    atomicMax(&g_sentpre[c], encf(mz + zb));
}

// ---------------- BN1 params ----------------
__global__ void kE1(const float* __restrict__ g1, const float* __restrict__ b1, int n){
    int c = threadIdx.x; // 128
    float cnt = (float)(n - g_cnt[SENTKEY]);
    float mu = g_sumz[c]/cnt;
    float var = g_sumz2[c]/cnt - mu*mu;
    var = fmaxf(var, 0.f);
    float a = g1[c] / sqrtf(var + BN_EPS);
    g_a1[c]=a; g_b1v[c]=b1[c]-mu*a;
}

// ---------------- final output ----------------
__global__ void kFinal(float* __restrict__ out){
    int i = blockIdx.x*blockDim.x + threadIdx.x;
    int stride = gridDim.x*blockDim.x;
    int U = g_U, sentseg = g_sentseg;
    const size_t total = (size_t)NSEG*128;
    for (size_t idx=i; idx<total; idx+=stride){
        int r = (int)(idx>>7), c = (int)(idx&127);
        float v = 0.f;
        if (r < U){
            float z = (r==sentseg) ? decf(g_sentpre[c]) : g_pre[idx];
            v = fmaxf(g_a1[c]*z + g_b1v[c], 0.f);
        }
        out[idx] = v;
    }
}

extern "C" void kernel_launch(void* const* d_in, const int* in_sizes, int n_in,
                              void* d_out, int out_size) {
    const float* pts = (const float*)d_in[0];
    const float* w0  = (const float*)d_in[1];
    const float* g0  = (const float*)d_in[2];
    const float* b0  = (const float*)d_in[3];
    const float* w1  = (const float*)d_in[4];
    const float* g1  = (const float*)d_in[5];
    const float* b1  = (const float*)d_in[6];
    float* out = (float*)d_out;
    int n = in_sizes[0] / 6;
    if (n > MAXN) n = MAXN;

    kInit<<<2048, 256>>>();
    kFill<<<1024, 256>>>(out);
    kA<<<2048, 256>>>(pts, n);
    kB1<<<NBLK, 1024>>>();
    kB2<<<1, 512>>>();
    kB3<<<NBLK, 1024>>>(out);
    kC<<<2048, 256>>>(n);
    kBN0<<<1024, 256>>>(pts, w0, n);
    kD1<<<1, 32>>>(g0, b0, n);
    kS1<<<512, 256>>>(pts, w0);
    kMega<<<1024, 256>>>(pts, w0, w1);
    kS2<<<512, 128>>>(w1);
    kE1<<<1, 128>>>(g1, b1, n);
    kFinal<<<8192, 256>>>(out);
}